// round 5
// baseline (speedup 1.0000x reference)
#include <cuda_runtime.h>
#include <math.h>

typedef unsigned long long u64;

#define CAP   65536
#define SORT_N 8192    // problem shape: M = N = 8192
#define QCH   2048     // queries per chunk (256 thr * 8 consecutive)
#define TSL   128      // targets per slice (tile = 4KB)
#define NBLK  296      // persistent grid (2 CTAs/SM on 148 SMs)
#define NRED  128
#define MAXSL 512

__device__ float4         g_cadQ[CAP];     // unsorted transformed cad (x,y,z,|v|^2)
__device__ float4         g_camQ[CAP];     // unsorted cam
__device__ float4         g_cadQs[CAP];    // z-sorted
__device__ float4         g_camQs[CAP];
__device__ float          g_cadTs[CAP*8];  // sorted dup fmt [x,x,y,y,z,z,h,h], h=|v|^2/2
__device__ float          g_camTs[CAP*8];
__device__ float          g_key[2*CAP];    // sort keys per list (z)
__device__ unsigned short g_sidx[2*CAP];   // sorted permutation per list
__device__ float          g_slr[8*MAXSL*2];// per (list,slice): [zlo, zhi]
__device__ unsigned       g_minbuf[2*CAP]; // per-(dir,p,query) best d2 bits
__device__ float          g_partial[NRED];
__device__ unsigned       g_ticket;

// ---------------- f32x2 helpers ---------------------------------------------
__device__ __forceinline__ u64 pack2(float lo, float hi) {
    u64 r; asm("mov.b64 %0, {%1, %2};" : "=l"(r) : "f"(lo), "f"(hi)); return r;
}
__device__ __forceinline__ void unpack2(u64 v, float& lo, float& hi) {
    asm("mov.b64 {%0, %1}, %2;" : "=f"(lo), "=f"(hi) : "l"(v));
}
__device__ __forceinline__ u64 fma2(u64 a, u64 b, u64 c) {
    u64 d; asm("fma.rn.f32x2 %0, %1, %2, %3;" : "=l"(d) : "l"(a), "l"(b), "l"(c)); return d;
}

// ---------------- transform builder (cheap, recomputed per thread) -----------
__device__ __forceinline__ void make_tf(const float* quat, const float* tra, int p, float tf[12]) {
    float a = quat[4*p], b = quat[4*p+1], c = quat[4*p+2], d = quat[4*p+3];
    float inv = rsqrtf(a*a + b*b + c*c + d*d);
    a *= inv; b *= inv; c *= inv; d *= inv;
    tf[0] = 1.f - 2.f*(c*c + d*d); tf[1] = 2.f*(b*c - a*d);       tf[2] = 2.f*(a*c + b*d);       tf[3]  = tra[3*p+0];
    tf[4] = 2.f*(b*c + a*d);       tf[5] = 1.f - 2.f*(b*b + d*d); tf[6] = 2.f*(c*d - a*b);       tf[7]  = tra[3*p+1];
    tf[8] = 2.f*(b*d - a*c);       tf[9] = 2.f*(a*b + c*d);       tf[10] = 1.f - 2.f*(b*b + c*c); tf[11] = tra[3*p+2];
}

// ---------------- launch 0: transforms + point prep + keys + minbuf ---------
__global__ void k_prep(const float* __restrict__ cad, const float* __restrict__ cam,
                       const float* __restrict__ quat, const float* __restrict__ tra,
                       float* __restrict__ out, int P, int M, int N, int total, int write_out) {
    int idx = blockIdx.x * blockDim.x + threadIdx.x;
    if (blockIdx.x == 0 && threadIdx.x < P && write_out) {
        float tf[12]; make_tf(quat, tra, threadIdx.x, tf);
        float* o = out + 1 + threadIdx.x * 16;
#pragma unroll
        for (int i = 0; i < 12; i++) o[i] = tf[i];
        o[12] = 0.f; o[13] = 0.f; o[14] = 0.f; o[15] = 1.f;
    }
    if (idx >= total) return;
    g_minbuf[idx] = 0x7f800000u;  // +inf

    if (idx < P * M) {
        int p = idx / M, m = idx % M;
        float tf[12]; make_tf(quat, tra, p, tf);
        const float* pt = cad + (size_t)idx * 3;
        float x = pt[0], y = pt[1], z = pt[2];
        float vx = tf[0]*x + tf[1]*y + tf[2]*z  + tf[3];
        float vy = tf[4]*x + tf[5]*y + tf[6]*z  + tf[7];
        float vz = tf[8]*x + tf[9]*y + tf[10]*z + tf[11];
        g_cadQ[idx] = make_float4(vx, vy, vz, vx*vx + vy*vy + vz*vz);
        g_key[p * SORT_N + m] = vz;
    } else {
        int jdx = idx - P * M;
        int p = jdx / N, m = jdx % N;
        const float* pt = cam + (size_t)jdx * 3;
        float vx = pt[0], vy = pt[1], vz = pt[2];
        g_camQ[jdx] = make_float4(vx, vy, vz, vx*vx + vy*vy + vz*vz);
        g_key[(P + p) * SORT_N + m] = vz;
    }
}

// ---------------- launch 1: bitonic sort per list (one CTA per list) --------
__global__ void __launch_bounds__(1024) k_sort() {
    __shared__ float sk[SORT_N];
    __shared__ unsigned short si[SORT_N];
    int l = blockIdx.x, tid = threadIdx.x;
    for (int i = tid; i < SORT_N; i += 1024) { sk[i] = g_key[l * SORT_N + i]; si[i] = (unsigned short)i; }
    __syncthreads();
    for (int k = 2; k <= SORT_N; k <<= 1) {
        for (int j = k >> 1; j > 0; j >>= 1) {
            for (int i = tid; i < SORT_N; i += 1024) {
                int ixj = i ^ j;
                if (ixj > i) {
                    float a = sk[i], b = sk[ixj];
                    bool up = ((i & k) == 0);
                    if (up ? (a > b) : (a < b)) {
                        sk[i] = b; sk[ixj] = a;
                        unsigned short tt = si[i]; si[i] = si[ixj]; si[ixj] = tt;
                    }
                }
            }
            __syncthreads();
        }
    }
    for (int i = tid; i < SORT_N; i += 1024) g_sidx[l * SORT_N + i] = si[i];
}

// ---------------- launch 2: gather into sorted arrays + slice ranges --------
__global__ void k_gather(int P, int total2) {
    int pos = blockIdx.x * blockDim.x + threadIdx.x;
    if (pos == 0) g_ticket = 0u;
    if (pos >= total2) return;
    int l = pos / SORT_N, i = pos % SORT_N;
    int s = g_sidx[pos];
    float4 q = (l < P) ? g_cadQ[l * SORT_N + s] : g_camQ[(l - P) * SORT_N + s];
    float h = 0.5f * q.w;
    int pp = (l < P) ? l : (l - P);
    if (l < P) g_cadQs[l * SORT_N + i] = q; else g_camQs[pp * SORT_N + i] = q;
    float* T = ((l < P) ? g_cadTs : g_camTs) + ((size_t)pp * SORT_N + i) * 8;
    T[0] = q.x; T[1] = q.x; T[2] = q.y; T[3] = q.y;
    T[4] = q.z; T[5] = q.z; T[6] = h;   T[7] = h;
    int sl = i / TSL;
    if ((i % TSL) == 0)       g_slr[(l * MAXSL + sl) * 2 + 0] = q.z;
    if ((i % TSL) == TSL - 1) g_slr[(l * MAXSL + sl) * 2 + 1] = q.z;
}

// ---------------- launch 3 (hot): chamfer with z-window culling -------------
__global__ void __launch_bounds__(256, 2) k_chamfer(int P, int M, int N,
                                                    int qcA, int tsA, int qcB, int tsB) {
    __shared__ __align__(16) float tile[TSL * 8];
    __shared__ int s_item;

    const int tid = threadIdx.x;
    const float INF = __int_as_float(0x7f800000);
    const int chunksA = P * qcA, chunksB = P * qcB;
    const int totalChunks = chunksA + chunksB;
    const int jmax = (tsA > tsB) ? tsA : tsB;
    const int totalTickets = jmax * totalChunks;

    for (;;) {
        __syncthreads();            // prev iter done with tile & s_item
        if (tid == 0) s_item = (int)atomicAdd(&g_ticket, 1u);
        __syncthreads();
        int t = s_item;
        if (t >= totalTickets) break;

        // ring-ordered decode: j-major so diagonals (j=0) run first
        int j = t / totalChunks, c = t % totalChunks;
        int p, qc, ns, nq, nt, minoff, tlist;
        const float4* Q;
        const float*  T;
        if (c < chunksA) {
            p = c / qcA; qc = c % qcA; ns = tsA; nq = M; nt = N;
            Q = g_cadQs + (size_t)p * M;
            T = g_camTs + (size_t)p * N * 8;
            minoff = p * M; tlist = P + p;
        } else {
            int cc = c - chunksA;
            p = cc / qcB; qc = cc % qcB; ns = tsB; nq = N; nt = M;
            Q = g_camQs + (size_t)p * N;
            T = g_cadTs + (size_t)p * M * 8;
            minoff = P * M + p * N; tlist = p;
        }
        if (j >= ns) continue;   // uniform across block

        int center = (qc * QCH + QCH / 2) / TSL; if (center >= ns) center = ns - 1;
        int off = (j & 1) ? (j + 1) / 2 : -(j / 2);
        int sl = (center + off) % ns; if (sl < 0) sl += ns;

        // ---- this thread's 8 CONSECUTIVE sorted queries + current bests ----
        int base = qc * QCH + tid * 8;
        float4 qv[8];
        float maxb = 0.f;
#pragma unroll
        for (int k = 0; k < 8; k++) {
            int i = base + k; if (i > nq - 1) i = nq - 1;
            qv[k] = Q[i];
            float bk = __uint_as_float(g_minbuf[minoff + i]);
            maxb = (k == 0) ? bk : fmaxf(maxb, bk);
        }
#pragma unroll
        for (int o = 16; o; o >>= 1) maxb = fmaxf(maxb, __shfl_xor_sync(0xffffffffu, maxb, o));
        float wzlo = __shfl_sync(0xffffffffu, qv[0].z, 0);
        float wzhi = __shfl_sync(0xffffffffu, qv[7].z, 31);

        // ---- cooperative tile load ----
        int tb = sl * TSL;
        int cnt = min(TSL, nt - tb);
        {
            const float4* src = (const float4*)(T + (size_t)tb * 8);
            float4* dst = (float4*)tile;
            for (int v = tid; v < cnt * 2; v += 256) dst[v] = src[v];
        }
        __syncthreads();

        // ---- per-warp cull: tile can't beat any of this warp's bests? ----
        float tzlo = g_slr[(tlist * MAXSL + sl) * 2 + 0];
        float tzhi = g_slr[(tlist * MAXSL + sl) * 2 + 1];
        float gap = fmaxf(0.f, fmaxf(tzlo - wzhi, wzlo - tzhi));
        if (gap * gap < maxb) {
            u64 qnx[4], qny[4], qnz[4];
            float mn0[4], mn1[4];
#pragma unroll
            for (int m = 0; m < 4; m++) {
                qnx[m] = pack2(-qv[2*m].x, -qv[2*m+1].x);
                qny[m] = pack2(-qv[2*m].y, -qv[2*m+1].y);
                qnz[m] = pack2(-qv[2*m].z, -qv[2*m+1].z);
                mn0[m] = INF; mn1[m] = INF;
            }

            int jj = 0;
            for (; jj + 4 <= cnt; jj += 4) {
                const float* tp = tile + jj * 8;
                ulonglong2 a0 = *(const ulonglong2*)(tp);
                ulonglong2 a1 = *(const ulonglong2*)(tp + 4);
                ulonglong2 b0 = *(const ulonglong2*)(tp + 8);
                ulonglong2 b1 = *(const ulonglong2*)(tp + 12);
                ulonglong2 c0 = *(const ulonglong2*)(tp + 16);
                ulonglong2 c1 = *(const ulonglong2*)(tp + 20);
                ulonglong2 d0 = *(const ulonglong2*)(tp + 24);
                ulonglong2 d1 = *(const ulonglong2*)(tp + 28);
#pragma unroll
                for (int m = 0; m < 4; m++) {
                    u64 gA = fma2(qnx[m], a0.x, a1.y);
                    u64 gB = fma2(qnx[m], b0.x, b1.y);
                    u64 gC = fma2(qnx[m], c0.x, c1.y);
                    u64 gD = fma2(qnx[m], d0.x, d1.y);
                    gA = fma2(qny[m], a0.y, gA);
                    gB = fma2(qny[m], b0.y, gB);
                    gC = fma2(qny[m], c0.y, gC);
                    gD = fma2(qny[m], d0.y, gD);
                    gA = fma2(qnz[m], a1.x, gA);
                    gB = fma2(qnz[m], b1.x, gB);
                    gC = fma2(qnz[m], c1.x, gC);
                    gD = fma2(qnz[m], d1.x, gD);
                    float alo, ahi, blo, bhi, clo, chi, dlo, dhi;
                    unpack2(gA, alo, ahi); unpack2(gB, blo, bhi);
                    unpack2(gC, clo, chi); unpack2(gD, dlo, dhi);
                    float lo01 = fminf(alo, blo), lo23 = fminf(clo, dlo);
                    float hi01 = fminf(ahi, bhi), hi23 = fminf(chi, dhi);
                    mn0[m] = fminf(mn0[m], fminf(lo01, lo23));
                    mn1[m] = fminf(mn1[m], fminf(hi01, hi23));
                }
            }
            for (; jj < cnt; jj++) {
                const float* tp = tile + jj * 8;
                ulonglong2 a0 = *(const ulonglong2*)(tp);
                ulonglong2 a1 = *(const ulonglong2*)(tp + 4);
#pragma unroll
                for (int m = 0; m < 4; m++) {
                    u64 gA = fma2(qnx[m], a0.x, a1.y);
                    gA = fma2(qny[m], a0.y, gA);
                    gA = fma2(qnz[m], a1.x, gA);
                    float a_lo, a_hi;
                    unpack2(gA, a_lo, a_hi);
                    mn0[m] = fminf(mn0[m], a_lo);
                    mn1[m] = fminf(mn1[m], a_hi);
                }
            }

            // d2 = 2*g + |q|^2 >= 0; bitwise uint min merges across items
#pragma unroll
            for (int m = 0; m < 4; m++) {
                int i0 = base + 2*m;     if (i0 > nq - 1) i0 = nq - 1;
                int i1 = base + 2*m + 1; if (i1 > nq - 1) i1 = nq - 1;
                float d0 = fmaxf(fmaf(2.f, mn0[m], qv[2*m].w),   0.f);
                float d1 = fmaxf(fmaf(2.f, mn1[m], qv[2*m+1].w), 0.f);
                atomicMin(g_minbuf + minoff + i0, __float_as_uint(d0));
                atomicMin(g_minbuf + minoff + i1, __float_as_uint(d1));
            }
        }
    }
}

// ---------------- launch 4: weighted sqrt-sum partials ----------------------
__global__ void k_red(const float* __restrict__ w, int P, int M, int N) {
    __shared__ float sh[256];
    int total = P * (M + N);
    float s = 0.f;
    for (int e = blockIdx.x * 256 + threadIdx.x; e < total; e += NRED * 256) {
        int p; float invc;
        if (e < P * M) { p = e / M; invc = 1.0f / (float)M; }
        else           { p = (e - P * M) / N; invc = 1.0f / (float)N; }
        s += w[p] * invc * sqrtf(__uint_as_float(g_minbuf[e]));
    }
    sh[threadIdx.x] = s;
    __syncthreads();
    for (int o = 128; o > 0; o >>= 1) {
        if (threadIdx.x < o) sh[threadIdx.x] += sh[threadIdx.x + o];
        __syncthreads();
    }
    if (threadIdx.x == 0) g_partial[blockIdx.x] = sh[0];
}

// ---------------- launch 5: deterministic final sum -------------------------
__global__ void k_fin(float* __restrict__ out) {
    if (threadIdx.x == 0) {
        float s = 0.f;
        for (int i = 0; i < NRED; i++) s += g_partial[i];
        out[0] = s;
    }
}

// ---------------- launcher ---------------------------------------------------
extern "C" void kernel_launch(void* const* d_in, const int* in_sizes, int n_in,
                              void* d_out, int out_size) {
    const float* cam  = (const float*)d_in[0];  // (P,N,3)
    const float* cad  = (const float*)d_in[1];  // (P,M,3)
    const float* wgt  = (const float*)d_in[2];  // (P,)
    const float* quat = (const float*)d_in[3];  // (P,4)
    const float* tra  = (const float*)d_in[4];  // (P,3,1)
    float* out = (float*)d_out;

    int P = in_sizes[2];
    int N = in_sizes[0] / (3 * P);
    int M = in_sizes[1] / (3 * P);
    int write_out = (out_size >= 1 + 16 * P) ? 1 : 0;

    int total = P * (M + N);
    k_prep<<<(total + 255) / 256, 256>>>(cad, cam, quat, tra, out, P, M, N, total, write_out); // 0

    k_sort<<<2 * P, 1024>>>();                                                                 // 1

    int total2 = 2 * P * SORT_N;
    k_gather<<<(total2 + 255) / 256, 256>>>(P, total2);                                        // 2

    int qcA = (M + QCH - 1) / QCH, tsA = (N + TSL - 1) / TSL;
    int qcB = (N + QCH - 1) / QCH, tsB = (M + TSL - 1) / TSL;
    k_chamfer<<<NBLK, 256>>>(P, M, N, qcA, tsA, qcB, tsB);                                     // 3 (hot)

    k_red<<<NRED, 256>>>(wgt, P, M, N);                                                        // 4
    k_fin<<<1, 1>>>(out);                                                                      // 5
}

// round 6
// speedup vs baseline: 1.3284x; 1.3284x over previous
#include <cuda_runtime.h>
#include <math.h>

typedef unsigned long long u64;
typedef unsigned int u32;

#define SORT_N 8192            // fixed problem shape: M = N = 8192
#define LISTS  8               // 2*P lists (P=4)
#define NB     256             // z-buckets per list
#define TSL    128             // targets per slice
#define NSL    (SORT_N / TSL)  // 64 slices per list
#define CHQ    256             // queries per chamfer block
#define NRED   64
#define ZMIN   (-16.0f)
#define ZSCALE (8.0f)          // NB / 32 range

#define CAPL (LISTS * SORT_N)

__device__ float4 g_Qu[CAPL];          // unsorted (x,y,z,|v|^2); lists 0..P-1 cad, P..2P-1 cam
__device__ float4 g_Qs[CAPL];          // bucket-sorted
__device__ float  g_T8[CAPL * 8];      // pair-interleaved targets [x0,x1,y0,y1,z0,z1,h0,h1]
__device__ float  g_key[CAPL];         // z keys
__device__ u32    g_hist[LISTS * NB];
__device__ u32    g_bstart[LISTS * NB];
__device__ u32    g_boff[LISTS * NB];
__device__ u32    g_slo[LISTS * NSL];  // per-slice z min (ordered-uint enc)
__device__ u32    g_shi[LISTS * NSL];  // per-slice z max
__device__ float  g_d2[CAPL];          // exact NN distance^2 per (list, sorted query)
__device__ double g_partial[NRED];

// ---------------- helpers ----------------------------------------------------
__device__ __forceinline__ u64 pack2(float lo, float hi) {
    u64 r; asm("mov.b64 %0, {%1, %2};" : "=l"(r) : "f"(lo), "f"(hi)); return r;
}
__device__ __forceinline__ void unpack2(u64 v, float& lo, float& hi) {
    asm("mov.b64 {%0, %1}, %2;" : "=f"(lo), "=f"(hi) : "l"(v));
}
__device__ __forceinline__ u64 fma2(u64 a, u64 b, u64 c) {
    u64 d; asm("fma.rn.f32x2 %0, %1, %2, %3;" : "=l"(d) : "l"(a), "l"(b), "l"(c)); return d;
}
__device__ __forceinline__ u32 encf(float f) {
    u32 u = __float_as_uint(f);
    return (u & 0x80000000u) ? ~u : (u | 0x80000000u);
}
__device__ __forceinline__ float decf(u32 u) {
    u32 b = (u & 0x80000000u) ? (u ^ 0x80000000u) : ~u;
    return __uint_as_float(b);
}
__device__ __forceinline__ int bucket_of(float z) {
    int b = (int)((z - ZMIN) * ZSCALE);
    return b < 0 ? 0 : (b > NB - 1 ? NB - 1 : b);
}
__device__ __forceinline__ void make_tf(const float* quat, const float* tra, int p, float tf[12]) {
    float a = quat[4*p], b = quat[4*p+1], c = quat[4*p+2], d = quat[4*p+3];
    float inv = rsqrtf(a*a + b*b + c*c + d*d);
    a *= inv; b *= inv; c *= inv; d *= inv;
    tf[0] = 1.f - 2.f*(c*c + d*d); tf[1] = 2.f*(b*c - a*d);        tf[2]  = 2.f*(a*c + b*d);        tf[3]  = tra[3*p+0];
    tf[4] = 2.f*(b*c + a*d);       tf[5] = 1.f - 2.f*(b*b + d*d);  tf[6]  = 2.f*(c*d - a*b);        tf[7]  = tra[3*p+1];
    tf[8] = 2.f*(b*d - a*c);       tf[9] = 2.f*(a*b + c*d);        tf[10] = 1.f - 2.f*(b*b + c*c);  tf[11] = tra[3*p+2];
}

// ---------------- launch 0: transforms + points + keys + histogram ----------
__global__ void k_prep(const float* __restrict__ cad, const float* __restrict__ cam,
                       const float* __restrict__ quat, const float* __restrict__ tra,
                       float* __restrict__ out, int P, int total, int write_out) {
    int idx = blockIdx.x * blockDim.x + threadIdx.x;
    if (blockIdx.x == 0 && threadIdx.x < P && write_out) {
        float tf[12]; make_tf(quat, tra, threadIdx.x, tf);
        float* o = out + 1 + threadIdx.x * 16;
#pragma unroll
        for (int i = 0; i < 12; i++) o[i] = tf[i];
        o[12] = 0.f; o[13] = 0.f; o[14] = 0.f; o[15] = 1.f;
    }
    if (idx >= total) return;

    float vx, vy, vz;
    if (idx < P * SORT_N) {
        int p = idx / SORT_N;
        float tf[12]; make_tf(quat, tra, p, tf);
        const float* pt = cad + (size_t)idx * 3;
        float x = pt[0], y = pt[1], z = pt[2];
        vx = tf[0]*x + tf[1]*y + tf[2]*z  + tf[3];
        vy = tf[4]*x + tf[5]*y + tf[6]*z  + tf[7];
        vz = tf[8]*x + tf[9]*y + tf[10]*z + tf[11];
    } else {
        const float* pt = cam + (size_t)(idx - P * SORT_N) * 3;
        vx = pt[0]; vy = pt[1]; vz = pt[2];
    }
    g_Qu[idx] = make_float4(vx, vy, vz, vx*vx + vy*vy + vz*vz);
    g_key[idx] = vz;
    int list = idx / SORT_N;
    atomicAdd(&g_hist[list * NB + bucket_of(vz)], 1u);
}

// ---------------- launch 1: per-list exclusive scan of histograms -----------
__global__ void __launch_bounds__(1024) k_scan(int nlists) {
    __shared__ u32 s[LISTS * NB];
    int tid = threadIdx.x;
    int tot = nlists * NB;
    for (int i = tid; i < tot; i += 1024) s[i] = g_hist[i];
    __syncthreads();
    for (int off = 1; off < NB; off <<= 1) {
        u32 v0 = 0, v1 = 0;
        int i0 = tid, i1 = tid + 1024;
        if (i0 < tot && (i0 % NB) >= off) v0 = s[i0 - off];
        if (i1 < tot && (i1 % NB) >= off) v1 = s[i1 - off];
        __syncthreads();
        if (i0 < tot) s[i0] += v0;
        if (i1 < tot) s[i1] += v1;
        __syncthreads();
    }
    for (int i = tid; i < tot; i += 1024) {
        u32 excl = s[i] - g_hist[i];       // inclusive -> exclusive
        g_bstart[i] = excl;
        g_boff[i]   = excl;
    }
}

// ---------------- launch 2: scatter into sorted layout + slice z-ranges -----
__global__ void k_scatter(int total) {
    int idx = blockIdx.x * blockDim.x + threadIdx.x;
    if (idx >= total) return;
    int list = idx / SORT_N;
    float z = g_key[idx];
    int b = bucket_of(z);
    u32 pos = atomicAdd(&g_boff[list * NB + b], 1u);
    float4 q = g_Qu[idx];
    g_Qs[(size_t)list * SORT_N + pos] = q;
    // pair-interleaved target store
    u32 pair = pos >> 1, lane = pos & 1;
    float* T = g_T8 + ((size_t)list * (SORT_N / 2) + pair) * 8;
    T[0 + lane] = q.x; T[2 + lane] = q.y; T[4 + lane] = q.z; T[6 + lane] = 0.5f * q.w;
    // slice z range
    u32 sl = pos / TSL;
    u32 e = encf(z);
    atomicMin(&g_slo[list * NSL + sl], e);
    atomicMax(&g_shi[list * NSL + sl], e);
}

// ---------------- launch 3 (hot): sorted-sweep exact NN ---------------------
__global__ void __launch_bounds__(256) k_chamfer(int P) {
    __shared__ __align__(16) float tile[TSL * 4];      // 64 pairs * 8 floats = 2KB
    __shared__ float env_lo[NSL], env_hi[NSL];
    __shared__ float s_zc;

    const int tid = threadIdx.x;
    const float INF = __int_as_float(0x7f800000);
    const int chunksPerList = SORT_N / CHQ;            // 32

    int c = blockIdx.x;
    int qlist = c / chunksPerList;
    int chunk = c % chunksPerList;
    int tlist = (qlist < P) ? qlist + P : qlist - P;

    int i = chunk * CHQ + tid;
    float4 q = g_Qs[(size_t)qlist * SORT_N + i];
    u64 qx = pack2(-q.x, -q.x);
    u64 qy = pack2(-q.y, -q.y);
    u64 qz = pack2(-q.z, -q.z);
    float best_g = INF;                                 // g = |t|^2/2 - q.t ; d2 = 2g + |q|^2

    // slice z-range envelopes (monotone): suffix-min of lo, prefix-max of hi
    if (tid < NSL)       env_lo[tid] = decf(g_slo[tlist * NSL + tid]);
    else if (tid < 2*NSL) env_hi[tid - NSL] = decf(g_shi[tlist * NSL + (tid - NSL)]);
    if (tid == 128) s_zc = q.z;
    __syncthreads();
    for (int off = 1; off < NSL; off <<= 1) {
        float a = 0.f, b = 0.f;
        if (tid < NSL) { a = env_lo[tid]; b = (tid + off < NSL) ? env_lo[tid + off] : a; }
        else if (tid < 2*NSL) { int t = tid - NSL; a = env_hi[t]; b = (t >= off) ? env_hi[t - off] : a; }
        __syncthreads();
        if (tid < NSL) env_lo[tid] = fminf(a, b);
        else if (tid < 2*NSL) env_hi[tid - NSL] = fmaxf(a, b);
        __syncthreads();
    }

    // starting slice: where the chunk-center z lands in the target list
    int sb = bucket_of(s_zc);
    int sl0 = (int)(g_bstart[tlist * NB + sb] >> 7);
    if (sl0 > NSL - 1) sl0 = NSL - 1;

    const float* Tbase = g_T8 + (size_t)tlist * (SORT_N / 2) * 8;

    // ---- sweep right (s >= sl0), then left; early exit via envelope bound ----
#pragma unroll 1
    for (int dir = 0; dir < 2; dir++) {
        int s = (dir == 0) ? sl0 : sl0 - 1;
        int step = (dir == 0) ? 1 : -1;
        int lim = (dir == 0) ? NSL : -1;
        while (s != lim) {
            float d2cur = fmaxf(fmaf(2.f, best_g, q.w), 0.f);
            float gap = (dir == 0) ? fmaxf(0.f, env_lo[s] - q.z)
                                   : fmaxf(0.f, q.z - env_hi[s]);
            if (!__syncthreads_or(gap * gap < d2cur)) break;

            // load slice tile: 64 pairs * 8 floats = 128 float4
            const float4* src = (const float4*)(Tbase + (size_t)s * TSL * 4);
            if (tid < 128) ((float4*)tile)[tid] = src[tid];
            __syncthreads();

            float mn0 = INF, mn1 = INF, mn2 = INF, mn3 = INF;
#pragma unroll 4
            for (int g4 = 0; g4 < TSL / 2; g4 += 4) {
                const float* tp = tile + g4 * 8;
                ulonglong2 a0 = *(const ulonglong2*)(tp);
                ulonglong2 a1 = *(const ulonglong2*)(tp + 4);
                ulonglong2 b0 = *(const ulonglong2*)(tp + 8);
                ulonglong2 b1 = *(const ulonglong2*)(tp + 12);
                ulonglong2 c0 = *(const ulonglong2*)(tp + 16);
                ulonglong2 c1 = *(const ulonglong2*)(tp + 20);
                ulonglong2 d0 = *(const ulonglong2*)(tp + 24);
                ulonglong2 d1 = *(const ulonglong2*)(tp + 28);
                u64 gA = fma2(qx, a0.x, a1.y);
                u64 gB = fma2(qx, b0.x, b1.y);
                u64 gC = fma2(qx, c0.x, c1.y);
                u64 gD = fma2(qx, d0.x, d1.y);
                gA = fma2(qy, a0.y, gA);
                gB = fma2(qy, b0.y, gB);
                gC = fma2(qy, c0.y, gC);
                gD = fma2(qy, d0.y, gD);
                gA = fma2(qz, a1.x, gA);
                gB = fma2(qz, b1.x, gB);
                gC = fma2(qz, c1.x, gC);
                gD = fma2(qz, d1.x, gD);
                float l0, h0v, l1, h1v, l2, h2v, l3, h3v;
                unpack2(gA, l0, h0v); unpack2(gB, l1, h1v);
                unpack2(gC, l2, h2v); unpack2(gD, l3, h3v);
                mn0 = fminf(mn0, fminf(l0, h0v));
                mn1 = fminf(mn1, fminf(l1, h1v));
                mn2 = fminf(mn2, fminf(l2, h2v));
                mn3 = fminf(mn3, fminf(l3, h3v));
            }
            best_g = fminf(best_g, fminf(fminf(mn0, mn1), fminf(mn2, mn3)));
            __syncthreads();       // tile reuse guard
            s += step;
        }
    }

    g_d2[(size_t)qlist * SORT_N + i] = fmaxf(fmaf(2.f, best_g, q.w), 0.f);
}

// ---------------- launch 4: weighted sqrt-sum partials (double acc) ---------
__global__ void k_red(const float* __restrict__ w, int P, int total) {
    __shared__ double sh[256];
    double s = 0.0;
    for (int e = blockIdx.x * 256 + threadIdx.x; e < total; e += NRED * 256) {
        int qlist = e / SORT_N;
        int p = (qlist < P) ? qlist : qlist - P;
        s += (double)(w[p] * sqrtf(g_d2[e]));
    }
    sh[threadIdx.x] = s;
    __syncthreads();
    for (int o = 128; o > 0; o >>= 1) {
        if (threadIdx.x < o) sh[threadIdx.x] += sh[threadIdx.x + o];
        __syncthreads();
    }
    if (threadIdx.x == 0) g_partial[blockIdx.x] = sh[0];
}

// ---------------- launch 5: final sum ----------------------------------------
__global__ void k_fin(float* __restrict__ out) {
    if (threadIdx.x == 0) {
        double s = 0.0;
        for (int i = 0; i < NRED; i++) s += g_partial[i];
        out[0] = (float)(s / (double)SORT_N);
    }
}

// ---------------- launch 6: reset mutable state for the next replay ---------
__global__ void k_zero() {
    int idx = blockIdx.x * blockDim.x + threadIdx.x;
    if (idx < LISTS * NB) g_hist[idx] = 0u;
    if (idx < LISTS * NSL) { g_slo[idx] = 0xFFFFFFFFu; g_shi[idx] = 0u; }
}

// ---------------- launcher ----------------------------------------------------
extern "C" void kernel_launch(void* const* d_in, const int* in_sizes, int n_in,
                              void* d_out, int out_size) {
    const float* cam  = (const float*)d_in[0];  // (P,N,3)
    const float* cad  = (const float*)d_in[1];  // (P,M,3)
    const float* wgt  = (const float*)d_in[2];  // (P,)
    const float* quat = (const float*)d_in[3];  // (P,4)
    const float* tra  = (const float*)d_in[4];  // (P,3,1)
    float* out = (float*)d_out;

    int P = in_sizes[2];
    int write_out = (out_size >= 1 + 16 * P) ? 1 : 0;
    int nlists = 2 * P;
    int total = nlists * SORT_N;

    // NOTE on state: g_hist/g_slo/g_shi start zeroed at module load; k_zero at the
    // end restores them for the next call. First call tolerates g_slo==0 (env_lo
    // decodes to NaN -> gap 0 -> conservative full sweep, still exact).

    k_prep<<<(total + 255) / 256, 256>>>(cad, cam, quat, tra, out, P, total, write_out); // 0
    k_scan<<<1, 1024>>>(nlists);                                                         // 1
    k_scatter<<<(total + 255) / 256, 256>>>(total);                                      // 2
    k_chamfer<<<nlists * (SORT_N / CHQ), 256>>>(P);                                      // 3 (hot)
    k_red<<<NRED, 256>>>(wgt, P, total);                                                 // 4
    k_fin<<<1, 1>>>(out);                                                                // 5
    k_zero<<<(LISTS * NB + 255) / 256, 256>>>();                                         // 6
}

// round 7
// speedup vs baseline: 1.6714x; 1.2582x over previous
#include <cuda_runtime.h>
#include <math.h>

typedef unsigned long long u64;
typedef unsigned int u32;

#define SORT_N 8192            // fixed problem shape: M = N = 8192
#define LISTS  8               // 2*P lists (P=4): 0..3 cad(transformed), 4..7 cam
#define NB     256             // z-buckets per list (width 0.125 over [-16,16])
#define TSL    128             // targets per slice
#define NSL    (SORT_N / TSL)  // 64
#define QCH    2048            // queries per chunk in main pass
#define NBLK   296             // persistent grid: exactly 2 CTAs/SM * 148 SMs
#define NRED   64
#define ZMIN   (-16.0f)
#define ZSCALE (8.0f)
#define CAPL   (LISTS * SORT_N)

__device__ float4 g_Qu[CAPL];          // unsorted (x,y,z,|v|^2)
__device__ float4 g_Qs[CAPL];          // bucket-sorted queries
__device__ float  g_Ts[CAPL * 8];      // sorted targets, dup fmt [x,x,y,y,z,z,h,h], h=|v|^2/2
__device__ float  g_key[CAPL];
__device__ u32    g_hist[LISTS * NB];
__device__ u32    g_bstart[LISTS * NB];
__device__ u32    g_boff[LISTS * NB];
__device__ u32    g_slo[LISTS * NSL];  // slice z min (ordered-uint)
__device__ u32    g_shi[LISTS * NSL];  // slice z max
__device__ u32    g_minbuf[CAPL];      // best d2 bits per (list, sorted query)
__device__ double g_partial[NRED];
__device__ u32    g_ticket;
__device__ u32    g_arrive;

// ---------------- helpers ----------------------------------------------------
__device__ __forceinline__ u64 pack2(float lo, float hi) {
    u64 r; asm("mov.b64 %0, {%1, %2};" : "=l"(r) : "f"(lo), "f"(hi)); return r;
}
__device__ __forceinline__ void unpack2(u64 v, float& lo, float& hi) {
    asm("mov.b64 {%0, %1}, %2;" : "=f"(lo), "=f"(hi) : "l"(v));
}
__device__ __forceinline__ u64 fma2(u64 a, u64 b, u64 c) {
    u64 d; asm("fma.rn.f32x2 %0, %1, %2, %3;" : "=l"(d) : "l"(a), "l"(b), "l"(c)); return d;
}
__device__ __forceinline__ u32 encf(float f) {
    u32 u = __float_as_uint(f);
    return (u & 0x80000000u) ? ~u : (u | 0x80000000u);
}
__device__ __forceinline__ float decf(u32 u) {
    u32 b = (u & 0x80000000u) ? (u ^ 0x80000000u) : ~u;
    return __uint_as_float(b);
}
__device__ __forceinline__ int bucket_of(float z) {
    int b = (int)((z - ZMIN) * ZSCALE);
    return b < 0 ? 0 : (b > NB - 1 ? NB - 1 : b);
}
__device__ __forceinline__ void make_tf(const float* quat, const float* tra, int p, float tf[12]) {
    float a = quat[4*p], b = quat[4*p+1], c = quat[4*p+2], d = quat[4*p+3];
    float inv = rsqrtf(a*a + b*b + c*c + d*d);
    a *= inv; b *= inv; c *= inv; d *= inv;
    tf[0] = 1.f - 2.f*(c*c + d*d); tf[1] = 2.f*(b*c - a*d);        tf[2]  = 2.f*(a*c + b*d);        tf[3]  = tra[3*p+0];
    tf[4] = 2.f*(b*c + a*d);       tf[5] = 1.f - 2.f*(b*b + d*d);  tf[6]  = 2.f*(c*d - a*b);        tf[7]  = tra[3*p+1];
    tf[8] = 2.f*(b*d - a*c);       tf[9] = 2.f*(a*b + c*d);        tf[10] = 1.f - 2.f*(b*b + c*c);  tf[11] = tra[3*p+2];
}

// ---------------- launch 0: transforms + points + keys + histogram ----------
__global__ void k_prep(const float* __restrict__ cad, const float* __restrict__ cam,
                       const float* __restrict__ quat, const float* __restrict__ tra,
                       float* __restrict__ out, int P, int total, int write_out) {
    int idx = blockIdx.x * blockDim.x + threadIdx.x;
    if (blockIdx.x == 0 && threadIdx.x < P && write_out) {
        float tf[12]; make_tf(quat, tra, threadIdx.x, tf);
        float* o = out + 1 + threadIdx.x * 16;
#pragma unroll
        for (int i = 0; i < 12; i++) o[i] = tf[i];
        o[12] = 0.f; o[13] = 0.f; o[14] = 0.f; o[15] = 1.f;
    }
    if (idx >= total) return;

    float vx, vy, vz;
    if (idx < P * SORT_N) {
        int p = idx / SORT_N;
        float tf[12]; make_tf(quat, tra, p, tf);
        const float* pt = cad + (size_t)idx * 3;
        float x = pt[0], y = pt[1], z = pt[2];
        vx = tf[0]*x + tf[1]*y + tf[2]*z  + tf[3];
        vy = tf[4]*x + tf[5]*y + tf[6]*z  + tf[7];
        vz = tf[8]*x + tf[9]*y + tf[10]*z + tf[11];
    } else {
        const float* pt = cam + (size_t)(idx - P * SORT_N) * 3;
        vx = pt[0]; vy = pt[1]; vz = pt[2];
    }
    g_Qu[idx] = make_float4(vx, vy, vz, vx*vx + vy*vy + vz*vz);
    g_key[idx] = vz;
    atomicAdd(&g_hist[(idx / SORT_N) * NB + bucket_of(vz)], 1u);
}

// ---------------- launch 1: per-list exclusive scan + counter resets --------
__global__ void __launch_bounds__(1024) k_scan(int nlists) {
    __shared__ u32 s[LISTS * NB];
    int tid = threadIdx.x;
    int tot = nlists * NB;
    if (tid == 0) { g_ticket = 0u; g_arrive = 0u; }
    for (int i = tid; i < tot; i += 1024) s[i] = g_hist[i];
    __syncthreads();
    for (int off = 1; off < NB; off <<= 1) {
        u32 v0 = 0, v1 = 0;
        int i0 = tid, i1 = tid + 1024;
        if (i0 < tot && (i0 % NB) >= off) v0 = s[i0 - off];
        if (i1 < tot && (i1 % NB) >= off) v1 = s[i1 - off];
        __syncthreads();
        if (i0 < tot) s[i0] += v0;
        if (i1 < tot) s[i1] += v1;
        __syncthreads();
    }
    for (int i = tid; i < tot; i += 1024) {
        u32 excl = s[i] - g_hist[i];
        g_bstart[i] = excl;
        g_boff[i]   = excl;
    }
}

// ---------------- launch 2: scatter into sorted layout + slice z-ranges -----
__global__ void k_scatter(int total) {
    int idx = blockIdx.x * blockDim.x + threadIdx.x;
    if (idx >= total) return;
    int list = idx / SORT_N;
    float z = g_key[idx];
    u32 pos = atomicAdd(&g_boff[list * NB + bucket_of(z)], 1u);
    float4 q = g_Qu[idx];
    g_Qs[(size_t)list * SORT_N + pos] = q;
    float h = 0.5f * q.w;
    float* T = g_Ts + ((size_t)list * SORT_N + pos) * 8;
    T[0] = q.x; T[1] = q.x; T[2] = q.y; T[3] = q.y;
    T[4] = q.z; T[5] = q.z; T[6] = h;   T[7] = h;
    u32 sl = pos / TSL;
    u32 e = encf(z);
    atomicMin(&g_slo[list * NSL + sl], e);
    atomicMax(&g_shi[list * NSL + sl], e);
}

// ---------------- launch 3 (hot): seed + barrier + skip-ticket chamfer ------
__global__ void __launch_bounds__(256, 2) k_chamfer(int P) {
    __shared__ __align__(16) float tile[TSL * 8];   // 4KB, dup fmt
    __shared__ int s_item;

    const int tid = threadIdx.x;
    const float INF = __int_as_float(0x7f800000);

    // ================= phase 1: seed (blocks 0..127, 512 queries each) ======
    if (blockIdx.x < LISTS * (SORT_N / 512)) {
        int b = blockIdx.x;
        int l = b / (SORT_N / 512);
        int chunk = b % (SORT_N / 512);
        int tlist = (l < P) ? l + P : l - P;
        int base = chunk * 512;
        const float4* Q = g_Qs + (size_t)l * SORT_N;
        const float*  T = g_Ts + (size_t)tlist * SORT_N * 8;

        int i0 = base + 2 * tid, i1 = i0 + 1;
        float4 A = Q[i0], B = Q[i1];
        u64 qnx = pack2(-A.x, -B.x);
        u64 qny = pack2(-A.y, -B.y);
        u64 qnz = pack2(-A.z, -B.z);
        float mn0 = INF, mn1 = INF;

        float zc = Q[base + 256].z;
        int sl0 = (int)(g_bstart[tlist * NB + bucket_of(zc)] >> 7);
        if (sl0 > NSL - 1) sl0 = NSL - 1;
        int slo = sl0 > 0 ? sl0 - 1 : 0;
        int shi = sl0 < NSL - 1 ? sl0 + 1 : NSL - 1;

        for (int s = slo; s <= shi; s++) {
            const float4* src = (const float4*)(T + (size_t)s * TSL * 8);
            ((float4*)tile)[tid] = src[tid];     // 256 float4 = full 4KB tile
            __syncthreads();
#pragma unroll 4
            for (int j = 0; j < TSL; j++) {
                const float* tp = tile + j * 8;
                ulonglong2 t0 = *(const ulonglong2*)(tp);
                ulonglong2 t1 = *(const ulonglong2*)(tp + 4);
                u64 g = fma2(qnx, t0.x, t1.y);
                g = fma2(qny, t0.y, g);
                g = fma2(qnz, t1.x, g);
                float glo, ghi; unpack2(g, glo, ghi);
                mn0 = fminf(mn0, glo);
                mn1 = fminf(mn1, ghi);
            }
            __syncthreads();
        }
        u32* mb = g_minbuf + (size_t)l * SORT_N;
        mb[i0] = __float_as_uint(fmaxf(fmaf(2.f, mn0, A.w), 0.f));
        mb[i1] = __float_as_uint(fmaxf(fmaf(2.f, mn1, B.w), 0.f));
    }

    // ================= barrier: all 296 blocks co-resident ==================
    __syncthreads();
    if (tid == 0) {
        __threadfence();
        atomicAdd(&g_arrive, 1u);
        while (*(volatile u32*)&g_arrive < (u32)gridDim.x) { }
    }
    __syncthreads();

    // ================= phase 2: ticketed tiles with seeded skipping =========
    const int totalItems = LISTS * (SORT_N / QCH) * NSL;   // 8*4*64 = 2048
    const int wid = tid >> 5, lane = tid & 31;

    for (;;) {
        __syncthreads();            // guards s_item and tile reuse
        if (tid == 0) s_item = (int)atomicAdd(&g_ticket, 1u);
        __syncthreads();
        int t = s_item;
        if (t >= totalItems) break;

        int l  = t >> 8;            // 256 items per list
        int qc = (t >> 6) & 3;
        int sl = t & 63;
        int tlist = (l < P) ? l + P : l - P;
        int minoff = l * SORT_N;
        const float4* Q = g_Qs + (size_t)l * SORT_N;
        const float*  T = g_Ts + (size_t)tlist * SORT_N * 8;

        // warp covers 256 CONSECUTIVE sorted queries: i = qc*2048 + wid*256 + k*32 + lane
        int wb = qc * QCH + wid * 256 + lane;
        u64 qnx[4], qny[4], qnz[4];
        float x2a[4], x2b[4];
        float maxb = 0.f, z_first = 0.f, z_last = 0.f;
#pragma unroll
        for (int m = 0; m < 4; m++) {
            int ia = wb + (2*m) * 32, ib = ia + 32;
            float4 A = Q[ia], B = Q[ib];
            qnx[m] = pack2(-A.x, -B.x);
            qny[m] = pack2(-A.y, -B.y);
            qnz[m] = pack2(-A.z, -B.z);
            x2a[m] = A.w; x2b[m] = B.w;
            if (m == 0) z_first = A.z;
            if (m == 3) z_last = B.z;
            float ba = __uint_as_float(__ldcg(g_minbuf + minoff + ia));
            float bb = __uint_as_float(__ldcg(g_minbuf + minoff + ib));
            maxb = fmaxf(maxb, fmaxf(ba, bb));
        }
#pragma unroll
        for (int o = 16; o; o >>= 1) maxb = fmaxf(maxb, __shfl_xor_sync(0xffffffffu, maxb, o));
        float wzlo = __shfl_sync(0xffffffffu, z_first, 0);
        float wzhi = __shfl_sync(0xffffffffu, z_last, 31);

        float tzlo = decf(g_slo[tlist * NSL + sl]);
        float tzhi = decf(g_shi[tlist * NSL + sl]);
        float gap = fmaxf(0.f, fmaxf(tzlo - wzhi, wzlo - tzhi));
        bool active = (gap * gap < maxb);

        if (!__syncthreads_or((int)active)) continue;   // whole block skips

        // cooperative tile load (4KB)
        ((float4*)tile)[tid] = ((const float4*)(T + (size_t)sl * TSL * 8))[tid];
        __syncthreads();

        if (active) {
            float mn0[4], mn1[4];
#pragma unroll
            for (int m = 0; m < 4; m++) { mn0[m] = INF; mn1[m] = INF; }

            for (int j = 0; j < TSL; j += 4) {
                const float* tp = tile + j * 8;
                ulonglong2 a0 = *(const ulonglong2*)(tp);
                ulonglong2 a1 = *(const ulonglong2*)(tp + 4);
                ulonglong2 b0 = *(const ulonglong2*)(tp + 8);
                ulonglong2 b1 = *(const ulonglong2*)(tp + 12);
                ulonglong2 c0 = *(const ulonglong2*)(tp + 16);
                ulonglong2 c1 = *(const ulonglong2*)(tp + 20);
                ulonglong2 d0 = *(const ulonglong2*)(tp + 24);
                ulonglong2 d1 = *(const ulonglong2*)(tp + 28);
#pragma unroll
                for (int m = 0; m < 4; m++) {
                    u64 gA = fma2(qnx[m], a0.x, a1.y);
                    u64 gB = fma2(qnx[m], b0.x, b1.y);
                    u64 gC = fma2(qnx[m], c0.x, c1.y);
                    u64 gD = fma2(qnx[m], d0.x, d1.y);
                    gA = fma2(qny[m], a0.y, gA);
                    gB = fma2(qny[m], b0.y, gB);
                    gC = fma2(qny[m], c0.y, gC);
                    gD = fma2(qny[m], d0.y, gD);
                    gA = fma2(qnz[m], a1.x, gA);
                    gB = fma2(qnz[m], b1.x, gB);
                    gC = fma2(qnz[m], c1.x, gC);
                    gD = fma2(qnz[m], d1.x, gD);
                    float alo, ahi, blo, bhi, clo, chi, dlo, dhi;
                    unpack2(gA, alo, ahi); unpack2(gB, blo, bhi);
                    unpack2(gC, clo, chi); unpack2(gD, dlo, dhi);
                    mn0[m] = fminf(mn0[m], fminf(fminf(alo, blo), fminf(clo, dlo)));
                    mn1[m] = fminf(mn1[m], fminf(fminf(ahi, bhi), fminf(chi, dhi)));
                }
            }
#pragma unroll
            for (int m = 0; m < 4; m++) {
                int ia = wb + (2*m) * 32, ib = ia + 32;
                float da = fmaxf(fmaf(2.f, mn0[m], x2a[m]), 0.f);
                float db = fmaxf(fmaf(2.f, mn1[m], x2b[m]), 0.f);
                atomicMin(g_minbuf + minoff + ia, __float_as_uint(da));
                atomicMin(g_minbuf + minoff + ib, __float_as_uint(db));
            }
        }
    }
}

// ---------------- launch 4: weighted sqrt-sum partials (double acc) ---------
__global__ void k_red(const float* __restrict__ w, int P, int total) {
    __shared__ double sh[256];
    double s = 0.0;
    for (int e = blockIdx.x * 256 + threadIdx.x; e < total; e += NRED * 256) {
        int l = e / SORT_N;
        int p = (l < P) ? l : l - P;
        s += (double)(w[p] * sqrtf(__uint_as_float(g_minbuf[e])));
    }
    sh[threadIdx.x] = s;
    __syncthreads();
    for (int o = 128; o > 0; o >>= 1) {
        if (threadIdx.x < o) sh[threadIdx.x] += sh[threadIdx.x + o];
        __syncthreads();
    }
    if (threadIdx.x == 0) g_partial[blockIdx.x] = sh[0];
}

// ---------------- launch 5: final sum ----------------------------------------
__global__ void k_fin(float* __restrict__ out) {
    if (threadIdx.x == 0) {
        double s = 0.0;
        for (int i = 0; i < NRED; i++) s += g_partial[i];
        out[0] = (float)(s / (double)SORT_N);
    }
}

// ---------------- launch 6: reset mutable state for the next replay ---------
__global__ void k_zero() {
    int idx = blockIdx.x * blockDim.x + threadIdx.x;
    if (idx < LISTS * NB) g_hist[idx] = 0u;
    if (idx < LISTS * NSL) { g_slo[idx] = 0xFFFFFFFFu; g_shi[idx] = 0u; }
    if (idx == 0) { g_ticket = 0u; g_arrive = 0u; }
}

// ---------------- launcher ----------------------------------------------------
extern "C" void kernel_launch(void* const* d_in, const int* in_sizes, int n_in,
                              void* d_out, int out_size) {
    const float* cam  = (const float*)d_in[0];  // (P,N,3)
    const float* cad  = (const float*)d_in[1];  // (P,M,3)
    const float* wgt  = (const float*)d_in[2];  // (P,)
    const float* quat = (const float*)d_in[3];  // (P,4)
    const float* tra  = (const float*)d_in[4];  // (P,3,1)
    float* out = (float*)d_out;

    int P = in_sizes[2];
    int write_out = (out_size >= 1 + 16 * P) ? 1 : 0;
    int nlists = 2 * P;
    int total = nlists * SORT_N;

    // State: g_hist/g_slo(0->NaN->conservative)/g_ticket/g_arrive are zero at
    // module load (first eager call is correct but unpruned); k_zero at the end
    // of every call restores proper values for the next (timed) replay.

    k_prep<<<(total + 255) / 256, 256>>>(cad, cam, quat, tra, out, P, total, write_out); // 0
    k_scan<<<1, 1024>>>(nlists);                                                         // 1
    k_scatter<<<(total + 255) / 256, 256>>>(total);                                      // 2
    k_chamfer<<<NBLK, 256>>>(P);                                                         // 3 (hot)
    k_red<<<NRED, 256>>>(wgt, P, total);                                                 // 4
    k_fin<<<1, 1>>>(out);                                                                // 5
    k_zero<<<(LISTS * NB + 255) / 256, 256>>>();                                         // 6
}